// round 10
// baseline (speedup 1.0000x reference)
#include <cuda_runtime.h>
#include <cstdint>

// Problem constants (fixed by the dataset)
#define NJ     25
#define CIN    256
#define HID    128
#define BATCH  256
#define MROWS  (BATCH * NJ)   // 6400 GEMM rows, contiguous
#define MT     32             // rows per K1 block
#define SPAD   260            // sS row stride: mod 32 = 4 -> conflict-free
#define BPAD   36             // W1 buffer row stride (32c chunk + 4 pad)
#define YPAD   132            // K2 sY row stride
#define CCH    32             // c columns per chunk
#define NCH    8              // chunks
#define NBUF   4              // pipeline buffers (depth-3 overlap)

#define BUFSZ     (64 * BPAD)              // 2304 floats per buffer
#define K1_SSRC   (NBUF * BUFSZ)           // 9216
#define K1_FLOATS (K1_SSRC + MT * SPAD)    // 17536
#define K1_BYTES  (K1_FLOATS * 4)          // 70144 B -> 3 blocks/SM

typedef unsigned long long ull;

__device__ float Yg[MROWS * HID];          // 3.27 MB scratch (L2-resident)

__device__ __forceinline__ void fma2(ull& d, ull a, ull b) {
    asm("fma.rn.f32x2 %0, %1, %2, %0;" : "+l"(d) : "l"(a), "l"(b));
}
__device__ __forceinline__ float lo2(ull v){ return __uint_as_float((unsigned)v); }
__device__ __forceinline__ float hi2(ull v){ return __uint_as_float((unsigned)(v >> 32)); }
__device__ __forceinline__ void cpasync16(uint32_t dst, const float* src) {
    asm volatile("cp.async.cg.shared.global [%0], [%1], 16;\n" :: "r"(dst), "l"(src));
}

// ============================================================================
// K1: Y = S @ W1^T.  Block = 32 M-rows x 64 h.  grid = 200*2 = 400.
// SCALAR FFMA version (diagnostic vs FFMA2 RF-bank penalty).
// Warp w: h-span [8w, 8w+8); thread: q=lane&3 -> h pair (8w+2q, +1);
// g=lane>>2 -> rows {g+8k}.  Depth-3 cp.async pipeline over 8 x 32-c chunks.
// ============================================================================
__global__ __launch_bounds__(256, 3)
void y_gemm_kernel(const float* __restrict__ src, const float* __restrict__ W1)
{
    extern __shared__ float smem[];
    float* sS = smem + K1_SSRC;

    const int tid   = threadIdx.x;
    const int mtile = blockIdx.x >> 1;
    const int half  = blockIdx.x & 1;
    const int hbase = half * 64;
    const int lane  = tid & 31, warp = tid >> 5;
    const int q     = lane & 3;
    const int g     = lane >> 2;
    const int row0  = mtile * MT;

    const uint32_t smemU32 = (uint32_t)__cvta_generic_to_shared(smem);

    // stage chunk ch into buffer buf: 64h x 32c = 512 float4, 2 per thread
    auto stage_chunk = [&](int ch, int buf) {
        const uint32_t dstb = smemU32 + (uint32_t)(buf * BUFSZ * 4);
        #pragma unroll
        for (int k = 0; k < 2; k++) {
            const int idx = k * 256 + tid;
            const int r = idx >> 3, c4 = idx & 7;
            cpasync16(dstb + (uint32_t)(r * BPAD + c4 * 4) * 4,
                      W1 + (size_t)(hbase + r) * CIN + ch * CCH + c4 * 4);
        }
    };

    // prologue: group0 = src tile + chunk0; group1 = c1; group2 = c2
    {
        #pragma unroll
        for (int k = 0; k < 8; k++) {            // 2048 float4: 32x256 S tile
            const int idx = k * 256 + tid;
            const int r = idx >> 6, c = idx & 63;
            cpasync16(smemU32 + (uint32_t)(K1_SSRC + r * SPAD + c * 4) * 4,
                      src + ((size_t)(row0 + r)) * CIN + c * 4);
        }
        stage_chunk(0, 0);
        asm volatile("cp.async.commit_group;\n");
        stage_chunk(1, 1);
        asm volatile("cp.async.commit_group;\n");
        stage_chunk(2, 2);
        asm volatile("cp.async.commit_group;\n");
    }

    float accA[4], accB[4];
    #pragma unroll
    for (int k = 0; k < 4; k++) { accA[k] = 0.0f; accB[k] = 0.0f; }

    #pragma unroll 1
    for (int ch = 0; ch < NCH; ch++) {
        // invariant: 3 groups outstanding at loop top -> this waits chunk ch
        asm volatile("cp.async.wait_group 2;\n");
        __syncthreads();   // chunk ch visible; buffer (ch+3)%4 free to refill

        if (ch + 3 < NCH) stage_chunk(ch + 3, (ch + 3) & 3);
        asm volatile("cp.async.commit_group;\n");   // may be empty: keeps count

        const float* wr = smem + (ch & 3) * BUFSZ + (warp * 8 + 2 * q) * BPAD;
        const float* sr = sS + g * SPAD + ch * CCH;

        #pragma unroll
        for (int c4i = 0; c4i < 8; c4i++) {
            const float4 w0 = *reinterpret_cast<const float4*>(wr + 4 * c4i);
            const float4 w1 = *reinterpret_cast<const float4*>(wr + BPAD + 4 * c4i);
            #pragma unroll
            for (int k = 0; k < 4; k++) {
                const float4 s =
                    *reinterpret_cast<const float4*>(sr + k * 8 * SPAD + 4 * c4i);
                accA[k] += s.x * w0.x + s.y * w0.y + s.z * w0.z + s.w * w0.w;
                accB[k] += s.x * w1.x + s.y * w1.y + s.z * w1.z + s.w * w1.w;
            }
        }
    }

    // write Y: float2 per (row, h-pair), rows g+8k
    #pragma unroll
    for (int k = 0; k < 4; k++) {
        const int grow = row0 + g + 8 * k;
        float2 v;
        v.x = accA[k];
        v.y = accB[k];
        *reinterpret_cast<float2*>(Yg + (size_t)grow * HID + hbase + warp * 8 + 2 * q) = v;
    }
}

// ============================================================================
// K2: epilogue.  Block = (batch, i-half): 128 threads, 4 warps.
// out[i,j] = c1*(z_j - z_i) + c2 * sum_h w2[h] |y_j[h] - y_i[h]|
// ============================================================================
__global__ __launch_bounds__(128, 6)
void edge_out_kernel(const float* __restrict__ alpha_p,
                     const float* __restrict__ W2,
                     float* __restrict__ out)
{
    __shared__ float sY[NJ * YPAD];      // 13.2 KB
    __shared__ float sW2[HID];
    __shared__ float sZ[NJ];

    const int tid   = threadIdx.x;
    const int b     = blockIdx.x >> 1;
    const int ihalf = blockIdx.x & 1;
    const int lane  = tid & 31, warp = tid >> 5;

    // stage Y[b] (25x128 contiguous) into padded sY + W2
    {
        const float4* y4 = reinterpret_cast<const float4*>(Yg + (size_t)b * NJ * HID);
        #pragma unroll
        for (int k = 0; k < 7; k++) {
            const int i = k * 128 + tid;
            if (i < NJ * HID / 4) {
                const int r = i >> 5, c = i & 31;
                *reinterpret_cast<float4*>(sY + r * YPAD + c * 4) = y4[i];
            }
        }
        sW2[tid] = W2[tid];
    }
    __syncthreads();

    // z[n] = sum_h W2[h] * y[n][h]  (warp per n, 4 warps)
    for (int n = warp; n < NJ; n += 4) {
        const float* yr = sY + n * YPAD;
        float v = sW2[lane]      * yr[lane]
                + sW2[lane + 32] * yr[lane + 32]
                + sW2[lane + 64] * yr[lane + 64]
                + sW2[lane + 96] * yr[lane + 96];
        #pragma unroll
        for (int o = 16; o > 0; o >>= 1)
            v += __shfl_xor_sync(0xffffffffu, v, o);
        if (lane == 0) sZ[n] = v;
    }
    __syncthreads();

    // phase 3: j on lanes; this block covers i in [i0, i0+iN)
    // dual accumulators per t (even/odd h4) halve the serial FMA chain depth
    {
        const float alpha = alpha_p[0];
        const float c1 = 0.5f * (1.0f + alpha);
        const float c2 = 0.5f * (1.0f - alpha);
        const ull NEG1  = 0xBF800000BF800000ull;
        const ull AMASK = 0x7FFFFFFF7FFFFFFFull;

        const int i0 = ihalf * 13;
        const int iN = ihalf ? 12 : 13;

        ull accP[4] = {0ull, 0ull, 0ull, 0ull};
        ull accQ[4] = {0ull, 0ull, 0ull, 0ull};
        const int jr = (lane < NJ) ? lane : (NJ - 1);    // clamp: stay in sY
        const float* yjrow = sY + jr * YPAD;

        #pragma unroll
        for (int hc = 0; hc < 8; hc++) {     // 16-h chunks
            const int hb = hc * 16;
            const ulonglong2 yjA = *reinterpret_cast<const ulonglong2*>(yjrow + hb);
            const ulonglong2 yjB = *reinterpret_cast<const ulonglong2*>(yjrow + hb + 4);
            const ulonglong2 yjC = *reinterpret_cast<const ulonglong2*>(yjrow + hb + 8);
            const ulonglong2 yjD = *reinterpret_cast<const ulonglong2*>(yjrow + hb + 12);
            const ulonglong2 wA  = *reinterpret_cast<const ulonglong2*>(sW2 + hb);
            const ulonglong2 wB  = *reinterpret_cast<const ulonglong2*>(sW2 + hb + 4);
            const ulonglong2 wC  = *reinterpret_cast<const ulonglong2*>(sW2 + hb + 8);
            const ulonglong2 wD  = *reinterpret_cast<const ulonglong2*>(sW2 + hb + 12);

            #pragma unroll
            for (int t = 0; t < 4; t++) {
                const int iv = warp + 4 * t;
                if (iv < iN) {
                    const float* yir = sY + (i0 + iv) * YPAD + hb;
                    const ulonglong2 yiA = *reinterpret_cast<const ulonglong2*>(yir);
                    const ulonglong2 yiB = *reinterpret_cast<const ulonglong2*>(yir + 4);
                    const ulonglong2 yiC = *reinterpret_cast<const ulonglong2*>(yir + 8);
                    const ulonglong2 yiD = *reinterpret_cast<const ulonglong2*>(yir + 12);
                    ull d;
                    d = yjA.x; fma2(d, yiA.x, NEG1); d &= AMASK; fma2(accP[t], d, wA.x);
                    d = yjA.y; fma2(d, yiA.y, NEG1); d &= AMASK; fma2(accQ[t], d, wA.y);
                    d = yjB.x; fma2(d, yiB.x, NEG1); d &= AMASK; fma2(accP[t], d, wB.x);
                    d = yjB.y; fma2(d, yiB.y, NEG1); d &= AMASK; fma2(accQ[t], d, wB.y);
                    d = yjC.x; fma2(d, yiC.x, NEG1); d &= AMASK; fma2(accP[t], d, wC.x);
                    d = yjC.y; fma2(d, yiC.y, NEG1); d &= AMASK; fma2(accQ[t], d, wC.y);
                    d = yjD.x; fma2(d, yiD.x, NEG1); d &= AMASK; fma2(accP[t], d, wD.x);
                    d = yjD.y; fma2(d, yiD.y, NEG1); d &= AMASK; fma2(accQ[t], d, wD.y);
                }
            }
        }

        float* outB = out + (size_t)b * NJ * NJ;
        if (lane < NJ) {
            const float zj = sZ[lane];
            #pragma unroll
            for (int t = 0; t < 4; t++) {
                const int iv = warp + 4 * t;
                if (iv < iN) {
                    const int i = i0 + iv;
                    const float S = lo2(accP[t]) + hi2(accP[t])
                                  + lo2(accQ[t]) + hi2(accQ[t]);
                    outB[i * NJ + lane] = c1 * (zj - sZ[i]) + c2 * S;
                }
            }
        }
    }
}

extern "C" void kernel_launch(void* const* d_in, const int* in_sizes, int n_in,
                              void* d_out, int out_size)
{
    // metadata order: src, heads, ends, pair_ids, W1, alpha, W2
    const float* src   = (const float*)d_in[0];
    const float* W1    = (const float*)d_in[4];
    const float* alpha = (const float*)d_in[5];
    const float* W2    = (const float*)d_in[6];
    float* out = (float*)d_out;

    cudaFuncSetAttribute(y_gemm_kernel,
                         cudaFuncAttributeMaxDynamicSharedMemorySize, K1_BYTES);

    const int batch  = in_sizes[0] / (NJ * CIN);     // 256
    const int mtiles = (batch * NJ) / MT;            // 200
    y_gemm_kernel<<<mtiles * 2, 256, K1_BYTES>>>(src, W1);
    edge_out_kernel<<<batch * 2, 128>>>(alpha, W2, out);
}

// round 12
// speedup vs baseline: 1.3756x; 1.3756x over previous
#include <cuda_runtime.h>
#include <cstdint>

// Problem constants (fixed by the dataset)
#define NJ     25
#define CIN    256
#define HID    128
#define BATCH  256
#define MROWS  (BATCH * NJ)

// ---- fused kernel smem layout (uint/float units) ----
#define APITCH 132               // A tile pitch (uint = bf16x2): conflict-free
#define WPITCH 36                // W chunk pitch (uint)
#define YPAD   132               // y pitch (float)
#define SAH    0                 // A hi tile: 32 x 132
#define SAL    4224              // A lo tile
#define SW     8448              // W bufs: [2 buf][2 part][128 x 36]
#define WPART  4608
#define SYF    8448              // y overlays W buf0 after GEMM (float idx)
#define SW2O   26880
#define SZO    27008
#define SMEM_FLOATS 27040
#define SMEM_BYTES  (SMEM_FLOATS * 4)    // 108160 -> occ 2

typedef unsigned long long ull;

__device__ unsigned Sh[MROWS * CIN / 2];   // bf16x2 hi of src
__device__ unsigned Sl[MROWS * CIN / 2];   // bf16x2 lo
__device__ unsigned Wh[HID * CIN / 2];     // bf16x2 hi of W1
__device__ unsigned Wl[HID * CIN / 2];

__device__ __forceinline__ void fma2(ull& d, ull a, ull b) {
    asm("fma.rn.f32x2 %0, %1, %2, %0;" : "+l"(d) : "l"(a), "l"(b));
}
__device__ __forceinline__ float lo2(ull v){ return __uint_as_float((unsigned)v); }
__device__ __forceinline__ float hi2(ull v){ return __uint_as_float((unsigned)(v >> 32)); }
__device__ __forceinline__ void cpasync16(uint32_t dst, const void* src) {
    asm volatile("cp.async.cg.shared.global [%0], [%1], 16;\n" :: "r"(dst), "l"(src));
}
__device__ __forceinline__ unsigned pk_bf16x2(float even, float odd) {
    unsigned r;   // low half = even, high half = odd
    asm("cvt.rn.bf16x2.f32 %0, %1, %2;" : "=r"(r) : "f"(odd), "f"(even));
    return r;
}
__device__ __forceinline__ void mma16816(float* d,
    unsigned a0, unsigned a1, unsigned a2, unsigned a3,
    unsigned b0, unsigned b1)
{
    asm volatile(
        "mma.sync.aligned.m16n8k16.row.col.f32.bf16.bf16.f32 "
        "{%0,%1,%2,%3},{%4,%5,%6,%7},{%8,%9},{%0,%1,%2,%3};"
        : "+f"(d[0]), "+f"(d[1]), "+f"(d[2]), "+f"(d[3])
        : "r"(a0), "r"(a1), "r"(a2), "r"(a3), "r"(b0), "r"(b1));
}

// ============================================================================
// K0: split S and W1 into bf16 hi/lo (x = hi + lo)
// ============================================================================
#define NS4 (MROWS * CIN / 4)
#define NW4 (HID * CIN / 4)
__global__ __launch_bounds__(256)
void convert_kernel(const float* __restrict__ src, const float* __restrict__ W1)
{
    const int idx = blockIdx.x * 256 + threadIdx.x;
    float4 v; unsigned *oh, *ol; int o;
    if (idx < NS4)            { v = reinterpret_cast<const float4*>(src)[idx];
                                oh = Sh; ol = Sl; o = idx * 2; }
    else if (idx < NS4 + NW4) { const int j = idx - NS4;
                                v = reinterpret_cast<const float4*>(W1)[j];
                                oh = Wh; ol = Wl; o = j * 2; }
    else return;

    const unsigned h0 = pk_bf16x2(v.x, v.y);
    const unsigned h1 = pk_bf16x2(v.z, v.w);
    const float fx = __uint_as_float(h0 << 16);
    const float fy = __uint_as_float(h0 & 0xFFFF0000u);
    const float fz = __uint_as_float(h1 << 16);
    const float fw = __uint_as_float(h1 & 0xFFFF0000u);
    oh[o] = h0; oh[o + 1] = h1;
    ol[o]     = pk_bf16x2(v.x - fx, v.y - fy);
    ol[o + 1] = pk_bf16x2(v.z - fz, v.w - fw);
}

// ============================================================================
// K1: fused per-batch kernel.  Phase 2 via mma.sync bf16 split-GEMM:
//   y[32pad x 128] = S[b] @ W1^T, D += Sh*Wh + Sh*Wl + Sl*Wh  (fp32 acc)
// Warp w owns h-span [16w, 16w+16) (2 n8 tiles) x both m16 tiles.
// Then z-reduction + phase 3 (R5-proven epilogue) in the same block.
// ============================================================================
__global__ __launch_bounds__(256, 2)
void fused_edge_kernel(const float* __restrict__ alpha_p,
                       const float* __restrict__ W2,
                       float* __restrict__ out)
{
    extern __shared__ float smemf[];
    unsigned* sm32 = reinterpret_cast<unsigned*>(smemf);
    float* sW2 = smemf + SW2O;
    float* sZ  = smemf + SZO;

    const int tid  = threadIdx.x;
    const int b    = blockIdx.x;
    const int lane = tid & 31, warp = tid >> 5;
    const int ra   = lane >> 2;       // fragment row/col group
    const int q    = lane & 3;        // thread-in-group

    const uint32_t smemB = (uint32_t)__cvta_generic_to_shared(smemf);

    // ---- prologue staging: A tiles (both parts) + W chunk0; then chunk1 ----
    {
        #pragma unroll
        for (int p = 0; p < 2; p++) {
            const unsigned* g = p ? Sl : Sh;
            for (int i = tid; i < 800; i += 256) {          // 25 rows x 32 grp
                const int r = i >> 5, c = i & 31;
                cpasync16(smemB + (uint32_t)((p ? SAL : SAH) + r * APITCH + c * 4) * 4,
                          g + (size_t)(b * NJ + r) * 128 + c * 4);
            }
        }
        #pragma unroll
        for (int p = 0; p < 2; p++) {                       // W chunk 0 -> buf0
            const unsigned* g = p ? Wl : Wh;
            #pragma unroll
            for (int k = 0; k < 4; k++) {
                const int i = k * 256 + tid;                // 1024 grp
                const int r = i >> 3, c8 = i & 7;
                cpasync16(smemB + (uint32_t)(SW + p * WPART + r * WPITCH + c8 * 4) * 4,
                          g + (size_t)r * 128 + c8 * 4);
            }
        }
        asm volatile("cp.async.commit_group;\n");
        #pragma unroll
        for (int p = 0; p < 2; p++) {                       // W chunk 1 -> buf1
            const unsigned* g = p ? Wl : Wh;
            #pragma unroll
            for (int k = 0; k < 4; k++) {
                const int i = k * 256 + tid;
                const int r = i >> 3, c8 = i & 7;
                cpasync16(smemB + (uint32_t)(SW + 9216 + p * WPART + r * WPITCH + c8 * 4) * 4,
                          g + (size_t)r * 128 + 32 + c8 * 4);
            }
        }
        asm volatile("cp.async.commit_group;\n");
        if (tid < HID) sW2[tid] = W2[tid];
    }

    // ---- phase 2: split GEMM over 4 k-chunks of 64 ----
    float acc[2][2][4];
    #pragma unroll
    for (int mt = 0; mt < 2; mt++)
        #pragma unroll
        for (int nt = 0; nt < 2; nt++)
            #pragma unroll
            for (int e = 0; e < 4; e++) acc[mt][nt][e] = 0.0f;

    const int h0 = warp * 16 + ra;
    const int h1 = h0 + 8;

    #pragma unroll 1
    for (int kc = 0; kc < 4; kc++) {
        asm volatile("cp.async.wait_group %0;\n" :: "n"(1) : "memory");
        if (kc == 3) asm volatile("cp.async.wait_group 0;\n" ::: "memory");
        __syncthreads();             // chunk kc visible to all

        const unsigned* bufW = sm32 + SW + (kc & 1) * 9216;

        #pragma unroll
        for (int split = 0; split < 3; split++) {
            const unsigned* aB = sm32 + (split == 2 ? SAL : SAH) + kc * 32;
            const unsigned* bB = bufW + (split == 1 ? WPART : 0);
            #pragma unroll
            for (int ks = 0; ks < 4; ks++) {
                const int kp = ks * 8 + q;
                const unsigned a0 = aB[(ra)      * APITCH + kp];
                const unsigned a1 = aB[(ra + 8)  * APITCH + kp];
                const unsigned a2 = aB[(ra)      * APITCH + kp + 4];
                const unsigned a3 = aB[(ra + 8)  * APITCH + kp + 4];
                const unsigned a4 = aB[(ra + 16) * APITCH + kp];
                const unsigned a5 = aB[(ra + 24) * APITCH + kp];
                const unsigned a6 = aB[(ra + 16) * APITCH + kp + 4];
                const unsigned a7 = aB[(ra + 24) * APITCH + kp + 4];
                const unsigned b0 = bB[h0 * WPITCH + ks * 8 + q];
                const unsigned b1 = bB[h0 * WPITCH + ks * 8 + q + 4];
                const unsigned b2 = bB[h1 * WPITCH + ks * 8 + q];
                const unsigned b3 = bB[h1 * WPITCH + ks * 8 + q + 4];
                mma16816(acc[0][0], a0, a1, a2, a3, b0, b1);
                mma16816(acc[0][1], a0, a1, a2, a3, b2, b3);
                mma16816(acc[1][0], a4, a5, a6, a7, b0, b1);
                mma16816(acc[1][1], a4, a5, a6, a7, b2, b3);
            }
        }

        __syncthreads();             // all reads of buf[kc&1] done
        if (kc + 2 < 4) {            // refill with chunk kc+2
            #pragma unroll
            for (int p = 0; p < 2; p++) {
                const unsigned* g = p ? Wl : Wh;
                #pragma unroll
                for (int k = 0; k < 4; k++) {
                    const int i = k * 256 + tid;
                    const int r = i >> 3, c8 = i & 7;
                    cpasync16(smemB + (uint32_t)(SW + (kc & 1) * 9216 + p * WPART
                                                 + r * WPITCH + c8 * 4) * 4,
                              g + (size_t)r * 128 + (kc + 2) * 32 + c8 * 4);
                }
            }
        }
        asm volatile("cp.async.commit_group;\n");   // may be empty
    }

    // ---- store y into sY (overlays W buf0: free — kc=3 read buf1) ----
    float* sY = smemf + SYF;
    #pragma unroll
    for (int mt = 0; mt < 2; mt++) {
        #pragma unroll
        for (int nt = 0; nt < 2; nt++) {
            const int col = warp * 16 + nt * 8 + 2 * q;
            const int r0 = mt * 16 + ra;
            if (r0 < NJ)
                *reinterpret_cast<float2*>(sY + r0 * YPAD + col) =
                    make_float2(acc[mt][nt][0], acc[mt][nt][1]);
            if (r0 + 8 < NJ)
                *reinterpret_cast<float2*>(sY + (r0 + 8) * YPAD + col) =
                    make_float2(acc[mt][nt][2], acc[mt][nt][3]);
        }
    }
    __syncthreads();

    // ---- z[n] = sum_h W2[h]*y[n][h] (warp per n) ----
    for (int n = warp; n < NJ; n += 8) {
        const float* yr = sY + n * YPAD;
        float v = sW2[lane]      * yr[lane]
                + sW2[lane + 32] * yr[lane + 32]
                + sW2[lane + 64] * yr[lane + 64]
                + sW2[lane + 96] * yr[lane + 96];
        #pragma unroll
        for (int o = 16; o > 0; o >>= 1)
            v += __shfl_xor_sync(0xffffffffu, v, o);
        if (lane == 0) sZ[n] = v;
    }
    __syncthreads();

    // ---- phase 3: j on lanes, i = warp + 8t; dual acc chains ----
    {
        const float alpha = alpha_p[0];
        const float c1 = 0.5f * (1.0f + alpha);
        const float c2 = 0.5f * (1.0f - alpha);
        const ull NEG1  = 0xBF800000BF800000ull;
        const ull AMASK = 0x7FFFFFFF7FFFFFFFull;

        ull accP[4] = {0ull, 0ull, 0ull, 0ull};
        ull accQ[4] = {0ull, 0ull, 0ull, 0ull};
        const int jr = (lane < NJ) ? lane : (NJ - 1);
        const float* yjrow = sY + jr * YPAD;

        #pragma unroll
        for (int hc = 0; hc < 8; hc++) {
            const int hb = hc * 16;
            const ulonglong2 yjA = *reinterpret_cast<const ulonglong2*>(yjrow + hb);
            const ulonglong2 yjB = *reinterpret_cast<const ulonglong2*>(yjrow + hb + 4);
            const ulonglong2 yjC = *reinterpret_cast<const ulonglong2*>(yjrow + hb + 8);
            const ulonglong2 yjD = *reinterpret_cast<const ulonglong2*>(yjrow + hb + 12);
            const ulonglong2 wA  = *reinterpret_cast<const ulonglong2*>(sW2 + hb);
            const ulonglong2 wB  = *reinterpret_cast<const ulonglong2*>(sW2 + hb + 4);
            const ulonglong2 wC  = *reinterpret_cast<const ulonglong2*>(sW2 + hb + 8);
            const ulonglong2 wD  = *reinterpret_cast<const ulonglong2*>(sW2 + hb + 12);

            #pragma unroll
            for (int t = 0; t < 4; t++) {
                const int i = warp + 8 * t;
                if (i < NJ) {
                    const float* yir = sY + i * YPAD + hb;
                    const ulonglong2 yiA = *reinterpret_cast<const ulonglong2*>(yir);
                    const ulonglong2 yiB = *reinterpret_cast<const ulonglong2*>(yir + 4);
                    const ulonglong2 yiC = *reinterpret_cast<const ulonglong2*>(yir + 8);
                    const ulonglong2 yiD = *reinterpret_cast<const ulonglong2*>(yir + 12);
                    ull d;
                    d = yjA.x; fma2(d, yiA.x, NEG1); d &= AMASK; fma2(accP[t], d, wA.x);
                    d = yjA.y; fma2(d, yiA.y, NEG1); d &= AMASK; fma2(accQ[t], d, wA.y);
                    d = yjB.x; fma2(d, yiB.x, NEG1); d &= AMASK; fma2(accP[t], d, wB.x);
                    d = yjB.y; fma2(d, yiB.y, NEG1); d &= AMASK; fma2(accQ[t], d, wB.y);
                    d = yjC.x; fma2(d, yiC.x, NEG1); d &= AMASK; fma2(accP[t], d, wC.x);
                    d = yjC.y; fma2(d, yiC.y, NEG1); d &= AMASK; fma2(accQ[t], d, wC.y);
                    d = yjD.x; fma2(d, yiD.x, NEG1); d &= AMASK; fma2(accP[t], d, wD.x);
                    d = yjD.y; fma2(d, yiD.y, NEG1); d &= AMASK; fma2(accQ[t], d, wD.y);
                }
            }
        }

        float* outB = out + (size_t)b * NJ * NJ;
        if (lane < NJ) {
            const float zj = sZ[lane];
            #pragma unroll
            for (int t = 0; t < 4; t++) {
                const int i = warp + 8 * t;
                if (i < NJ) {
                    const float S = lo2(accP[t]) + hi2(accP[t])
                                  + lo2(accQ[t]) + hi2(accQ[t]);
                    outB[i * NJ + lane] = c1 * (zj - sZ[i]) + c2 * S;
                }
            }
        }
    }
}

extern "C" void kernel_launch(void* const* d_in, const int* in_sizes, int n_in,
                              void* d_out, int out_size)
{
    // metadata order: src, heads, ends, pair_ids, W1, alpha, W2
    const float* src   = (const float*)d_in[0];
    const float* W1    = (const float*)d_in[4];
    const float* alpha = (const float*)d_in[5];
    const float* W2    = (const float*)d_in[6];
    float* out = (float*)d_out;

    cudaFuncSetAttribute(fused_edge_kernel,
                         cudaFuncAttributeMaxDynamicSharedMemorySize, SMEM_BYTES);

    const int batch = in_sizes[0] / (NJ * CIN);          // 256
    convert_kernel<<<(NS4 + NW4 + 255) / 256, 256>>>(src, W1);
    fused_edge_kernel<<<batch, 256, SMEM_BYTES>>>(alpha, W2, out);
}

// round 13
// speedup vs baseline: 1.5050x; 1.0941x over previous
#include <cuda_runtime.h>
#include <cstdint>

// Problem constants (fixed by the dataset)
#define NJ     25
#define CIN    256
#define HID    128
#define BATCH  256
#define MROWS  (BATCH * NJ)

// ---- fused kernel smem layout (float/uint units) ----
#define APITCH 132               // A tile pitch (uint = bf16x2)
#define WPITCH 36                // W chunk pitch (uint)
#define WPART  4608              // 128 x 36 per part
#define YPAD   132               // y pitch (float)
#define SAH    0                 // A hi tile: 32 x 132 (rows 25-31 garbage)
#define SAL    4224
#define SW     8448              // W bufs: [2 buf][2 part][128 x 36]
#define SRCF   (SW + 9216)       // fp32 src staging, overlays W buf1 (6400 used)
#define SYF    8448              // y overlays W buf0 after GEMM
#define SW2O   26880
#define SZO    27008
#define SMEM_FLOATS 27040
#define SMEM_BYTES  (SMEM_FLOATS * 4)    // 108160 -> occ 2

typedef unsigned long long ull;

__device__ unsigned Wh[HID * CIN / 2];     // bf16x2 hi of W1
__device__ unsigned Wl[HID * CIN / 2];

__device__ __forceinline__ void fma2(ull& d, ull a, ull b) {
    asm("fma.rn.f32x2 %0, %1, %2, %0;" : "+l"(d) : "l"(a), "l"(b));
}
__device__ __forceinline__ float lo2(ull v){ return __uint_as_float((unsigned)v); }
__device__ __forceinline__ float hi2(ull v){ return __uint_as_float((unsigned)(v >> 32)); }
__device__ __forceinline__ void cpasync16(uint32_t dst, const void* src) {
    asm volatile("cp.async.cg.shared.global [%0], [%1], 16;\n" :: "r"(dst), "l"(src));
}
__device__ __forceinline__ unsigned pk_bf16x2(float even, float odd) {
    unsigned r;   // low half = even, high half = odd
    asm("cvt.rn.bf16x2.f32 %0, %1, %2;" : "=r"(r) : "f"(odd), "f"(even));
    return r;
}
__device__ __forceinline__ void mma16816(float* d,
    unsigned a0, unsigned a1, unsigned a2, unsigned a3,
    unsigned b0, unsigned b1)
{
    asm volatile(
        "mma.sync.aligned.m16n8k16.row.col.f32.bf16.bf16.f32 "
        "{%0,%1,%2,%3},{%4,%5,%6,%7},{%8,%9},{%0,%1,%2,%3};"
        : "+f"(d[0]), "+f"(d[1]), "+f"(d[2]), "+f"(d[3])
        : "r"(a0), "r"(a1), "r"(a2), "r"(a3), "r"(b0), "r"(b1));
}

// ============================================================================
// K0: split W1 only into bf16 hi/lo (src is converted in-block)
// ============================================================================
#define NW4 (HID * CIN / 4)      // 8192 float4
__global__ __launch_bounds__(256)
void convert_w_kernel(const float* __restrict__ W1)
{
    const int idx = blockIdx.x * 256 + threadIdx.x;
    if (idx >= NW4) return;
    const float4 v = reinterpret_cast<const float4*>(W1)[idx];
    const int o = idx * 2;
    const unsigned h0 = pk_bf16x2(v.x, v.y);
    const unsigned h1 = pk_bf16x2(v.z, v.w);
    const float fx = __uint_as_float(h0 << 16);
    const float fy = __uint_as_float(h0 & 0xFFFF0000u);
    const float fz = __uint_as_float(h1 << 16);
    const float fw = __uint_as_float(h1 & 0xFFFF0000u);
    Wh[o] = h0; Wh[o + 1] = h1;
    Wl[o]     = pk_bf16x2(v.x - fx, v.y - fy);
    Wl[o + 1] = pk_bf16x2(v.z - fz, v.w - fw);
}

// ============================================================================
// K1: fused per-batch kernel.  In-block src->bf16 hi/lo convert, then
//   y = S @ W1^T via mma.sync split GEMM (Sh*Wh + Sh*Wl + Sl*Wh, fp32 acc),
//   then z-reduction + phase 3 epilogue (R12-proven).
// ============================================================================
__global__ __launch_bounds__(256, 2)
void fused_edge_kernel(const float* __restrict__ src,
                       const float* __restrict__ alpha_p,
                       const float* __restrict__ W2,
                       float* __restrict__ out)
{
    extern __shared__ float smemf[];
    unsigned* sm32 = reinterpret_cast<unsigned*>(smemf);
    float* sW2 = smemf + SW2O;
    float* sZ  = smemf + SZO;

    const int tid  = threadIdx.x;
    const int b    = blockIdx.x;
    const int lane = tid & 31, warp = tid >> 5;
    const int ra   = lane >> 2;       // fragment row/col group
    const int q    = lane & 3;        // thread-in-group

    const uint32_t smemB = (uint32_t)__cvta_generic_to_shared(smemf);

    // ---- G0: src fp32 tile -> SRCF (overlays W buf1).  G1: W chunk0 -> buf0.
    {
        const float* srcB = src + (size_t)b * NJ * CIN;
        #pragma unroll
        for (int k = 0; k < 7; k++) {              // 1600 float4
            const int idx = k * 256 + tid;
            if (idx < 1600)
                cpasync16(smemB + (uint32_t)(SRCF + idx * 4) * 4, srcB + idx * 4);
        }
        asm volatile("cp.async.commit_group;\n");  // G0
        #pragma unroll
        for (int p = 0; p < 2; p++) {
            const unsigned* g = p ? Wl : Wh;
            #pragma unroll
            for (int k = 0; k < 4; k++) {
                const int i = k * 256 + tid;       // 1024 grp
                const int r = i >> 3, c8 = i & 7;
                cpasync16(smemB + (uint32_t)(SW + p * WPART + r * WPITCH + c8 * 4) * 4,
                          g + (size_t)r * 128 + c8 * 4);
            }
        }
        asm volatile("cp.async.commit_group;\n");  // G1
        if (tid < HID) sW2[tid] = W2[tid];
    }

    // ---- convert src -> A hi/lo tiles (W chunk0 load continues async) ----
    asm volatile("cp.async.wait_group 1;\n" ::: "memory");   // G0 done
    __syncthreads();
    {
        #pragma unroll
        for (int k = 0; k < 7; k++) {
            const int idx = k * 256 + tid;
            if (idx < 1600) {
                const int r = idx >> 6, c4 = idx & 63;       // 64 float4/row
                const float4 v = *reinterpret_cast<const float4*>(smemf + SRCF + idx * 4);
                const unsigned h0 = pk_bf16x2(v.x, v.y);
                const unsigned h1 = pk_bf16x2(v.z, v.w);
                const float fx = __uint_as_float(h0 << 16);
                const float fy = __uint_as_float(h0 & 0xFFFF0000u);
                const float fz = __uint_as_float(h1 << 16);
                const float fw = __uint_as_float(h1 & 0xFFFF0000u);
                const unsigned l0 = pk_bf16x2(v.x - fx, v.y - fy);
                const unsigned l1 = pk_bf16x2(v.z - fz, v.w - fw);
                const int o = r * APITCH + c4 * 2;
                sm32[SAH + o] = h0; sm32[SAH + o + 1] = h1;
                sm32[SAL + o] = l0; sm32[SAL + o + 1] = l1;
            }
        }
    }
    __syncthreads();      // converts done; SRCF (buf1 region) free to overwrite

    // ---- G2: W chunk1 -> buf1 ----
    {
        #pragma unroll
        for (int p = 0; p < 2; p++) {
            const unsigned* g = p ? Wl : Wh;
            #pragma unroll
            for (int k = 0; k < 4; k++) {
                const int i = k * 256 + tid;
                const int r = i >> 3, c8 = i & 7;
                cpasync16(smemB + (uint32_t)(SW + 9216 + p * WPART + r * WPITCH + c8 * 4) * 4,
                          g + (size_t)r * 128 + 32 + c8 * 4);
            }
        }
        asm volatile("cp.async.commit_group;\n");  // G2
    }

    // ---- phase 2: split GEMM over 4 k-chunks of 64, hoisted fragments ----
    float acc[2][2][4];
    #pragma unroll
    for (int mt = 0; mt < 2; mt++)
        #pragma unroll
        for (int nt = 0; nt < 2; nt++)
            #pragma unroll
            for (int e = 0; e < 4; e++) acc[mt][nt][e] = 0.0f;

    const int h0 = warp * 16 + ra;
    const int h1 = h0 + 8;

    #pragma unroll 1
    for (int kc = 0; kc < 4; kc++) {
        asm volatile("cp.async.wait_group %0;\n" :: "n"(1) : "memory");
        if (kc == 3) asm volatile("cp.async.wait_group 0;\n" ::: "memory");
        __syncthreads();             // chunk kc visible to all

        const unsigned* bufW = sm32 + SW + (kc & 1) * 9216;
        const unsigned* aH   = sm32 + SAH + kc * 32;
        const unsigned* aL   = sm32 + SAL + kc * 32;

        #pragma unroll
        for (int ks = 0; ks < 4; ks++) {
            const int kp = ks * 8 + q;
            // A fragments (hi & lo), shared across splits
            const unsigned aH0 = aH[(ra)      * APITCH + kp];
            const unsigned aH1 = aH[(ra + 8)  * APITCH + kp];
            const unsigned aH2 = aH[(ra)      * APITCH + kp + 4];
            const unsigned aH3 = aH[(ra + 8)  * APITCH + kp + 4];
            const unsigned aH4 = aH[(ra + 16) * APITCH + kp];
            const unsigned aH5 = aH[(ra + 24) * APITCH + kp];
            const unsigned aH6 = aH[(ra + 16) * APITCH + kp + 4];
            const unsigned aH7 = aH[(ra + 24) * APITCH + kp + 4];
            const unsigned aL0 = aL[(ra)      * APITCH + kp];
            const unsigned aL1 = aL[(ra + 8)  * APITCH + kp];
            const unsigned aL2 = aL[(ra)      * APITCH + kp + 4];
            const unsigned aL3 = aL[(ra + 8)  * APITCH + kp + 4];
            const unsigned aL4 = aL[(ra + 16) * APITCH + kp];
            const unsigned aL5 = aL[(ra + 24) * APITCH + kp];
            const unsigned aL6 = aL[(ra + 16) * APITCH + kp + 4];
            const unsigned aL7 = aL[(ra + 24) * APITCH + kp + 4];
            // B fragments (hi & lo parts)
            const unsigned bH0 = bufW[h0 * WPITCH + kp];
            const unsigned bH1 = bufW[h0 * WPITCH + kp + 4];
            const unsigned bH2 = bufW[h1 * WPITCH + kp];
            const unsigned bH3 = bufW[h1 * WPITCH + kp + 4];
            const unsigned bL0 = bufW[WPART + h0 * WPITCH + kp];
            const unsigned bL1 = bufW[WPART + h0 * WPITCH + kp + 4];
            const unsigned bL2 = bufW[WPART + h1 * WPITCH + kp];
            const unsigned bL3 = bufW[WPART + h1 * WPITCH + kp + 4];

            // Sh*Wh
            mma16816(acc[0][0], aH0, aH1, aH2, aH3, bH0, bH1);
            mma16816(acc[0][1], aH0, aH1, aH2, aH3, bH2, bH3);
            mma16816(acc[1][0], aH4, aH5, aH6, aH7, bH0, bH1);
            mma16816(acc[1][1], aH4, aH5, aH6, aH7, bH2, bH3);
            // Sh*Wl
            mma16816(acc[0][0], aH0, aH1, aH2, aH3, bL0, bL1);
            mma16816(acc[0][1], aH0, aH1, aH2, aH3, bL2, bL3);
            mma16816(acc[1][0], aH4, aH5, aH6, aH7, bL0, bL1);
            mma16816(acc[1][1], aH4, aH5, aH6, aH7, bL2, bL3);
            // Sl*Wh
            mma16816(acc[0][0], aL0, aL1, aL2, aL3, bH0, bH1);
            mma16816(acc[0][1], aL0, aL1, aL2, aL3, bH2, bH3);
            mma16816(acc[1][0], aL4, aL5, aL6, aL7, bH0, bH1);
            mma16816(acc[1][1], aL4, aL5, aL6, aL7, bH2, bH3);
        }

        __syncthreads();             // all reads of buf[kc&1] done
        if (kc + 2 < 4) {            // refill with chunk kc+2
            #pragma unroll
            for (int p = 0; p < 2; p++) {
                const unsigned* g = p ? Wl : Wh;
                #pragma unroll
                for (int k = 0; k < 4; k++) {
                    const int i = k * 256 + tid;
                    const int r = i >> 3, c8 = i & 7;
                    cpasync16(smemB + (uint32_t)(SW + (kc & 1) * 9216 + p * WPART
                                                 + r * WPITCH + c8 * 4) * 4,
                              g + (size_t)r * 128 + (kc + 2) * 32 + c8 * 4);
                }
            }
        }
        asm volatile("cp.async.commit_group;\n");   // may be empty
    }

    // ---- store y into sY (overlays W buf0: last read at kc=2) ----
    float* sY = smemf + SYF;
    #pragma unroll
    for (int mt = 0; mt < 2; mt++) {
        #pragma unroll
        for (int nt = 0; nt < 2; nt++) {
            const int col = warp * 16 + nt * 8 + 2 * q;
            const int r0 = mt * 16 + ra;
            if (r0 < NJ)
                *reinterpret_cast<float2*>(sY + r0 * YPAD + col) =
                    make_float2(acc[mt][nt][0], acc[mt][nt][1]);
            if (r0 + 8 < NJ)
                *reinterpret_cast<float2*>(sY + (r0 + 8) * YPAD + col) =
                    make_float2(acc[mt][nt][2], acc[mt][nt][3]);
        }
    }
    __syncthreads();

    // ---- z[n] = sum_h W2[h]*y[n][h] (warp per n) ----
    for (int n = warp; n < NJ; n += 8) {
        const float* yr = sY + n * YPAD;
        float v = sW2[lane]      * yr[lane]
                + sW2[lane + 32] * yr[lane + 32]
                + sW2[lane + 64] * yr[lane + 64]
                + sW2[lane + 96] * yr[lane + 96];
        #pragma unroll
        for (int o = 16; o > 0; o >>= 1)
            v += __shfl_xor_sync(0xffffffffu, v, o);
        if (lane == 0) sZ[n] = v;
    }
    __syncthreads();

    // ---- phase 3: j on lanes, i = warp + 8t; dual acc chains ----
    {
        const float alpha = alpha_p[0];
        const float c1 = 0.5f * (1.0f + alpha);
        const float c2 = 0.5f * (1.0f - alpha);
        const ull NEG1  = 0xBF800000BF800000ull;
        const ull AMASK = 0x7FFFFFFF7FFFFFFFull;

        ull accP[4] = {0ull, 0ull, 0ull, 0ull};
        ull accQ[4] = {0ull, 0ull, 0ull, 0ull};
        const int jr = (lane < NJ) ? lane : (NJ - 1);
        const float* yjrow = sY + jr * YPAD;

        #pragma unroll
        for (int hc = 0; hc < 8; hc++) {
            const int hb = hc * 16;
            const ulonglong2 yjA = *reinterpret_cast<const ulonglong2*>(yjrow + hb);
            const ulonglong2 yjB = *reinterpret_cast<const ulonglong2*>(yjrow + hb + 4);
            const ulonglong2 yjC = *reinterpret_cast<const ulonglong2*>(yjrow + hb + 8);
            const ulonglong2 yjD = *reinterpret_cast<const ulonglong2*>(yjrow + hb + 12);
            const ulonglong2 wA  = *reinterpret_cast<const ulonglong2*>(sW2 + hb);
            const ulonglong2 wB  = *reinterpret_cast<const ulonglong2*>(sW2 + hb + 4);
            const ulonglong2 wC  = *reinterpret_cast<const ulonglong2*>(sW2 + hb + 8);
            const ulonglong2 wD  = *reinterpret_cast<const ulonglong2*>(sW2 + hb + 12);

            #pragma unroll
            for (int t = 0; t < 4; t++) {
                const int i = warp + 8 * t;
                if (i < NJ) {
                    const float* yir = sY + i * YPAD + hb;
                    const ulonglong2 yiA = *reinterpret_cast<const ulonglong2*>(yir);
                    const ulonglong2 yiB = *reinterpret_cast<const ulonglong2*>(yir + 4);
                    const ulonglong2 yiC = *reinterpret_cast<const ulonglong2*>(yir + 8);
                    const ulonglong2 yiD = *reinterpret_cast<const ulonglong2*>(yir + 12);
                    ull d;
                    d = yjA.x; fma2(d, yiA.x, NEG1); d &= AMASK; fma2(accP[t], d, wA.x);
                    d = yjA.y; fma2(d, yiA.y, NEG1); d &= AMASK; fma2(accQ[t], d, wA.y);
                    d = yjB.x; fma2(d, yiB.x, NEG1); d &= AMASK; fma2(accP[t], d, wB.x);
                    d = yjB.y; fma2(d, yiB.y, NEG1); d &= AMASK; fma2(accQ[t], d, wB.y);
                    d = yjC.x; fma2(d, yiC.x, NEG1); d &= AMASK; fma2(accP[t], d, wC.x);
                    d = yjC.y; fma2(d, yiC.y, NEG1); d &= AMASK; fma2(accQ[t], d, wC.y);
                    d = yjD.x; fma2(d, yiD.x, NEG1); d &= AMASK; fma2(accP[t], d, wD.x);
                    d = yjD.y; fma2(d, yiD.y, NEG1); d &= AMASK; fma2(accQ[t], d, wD.y);
                }
            }
        }

        float* outB = out + (size_t)b * NJ * NJ;
        if (lane < NJ) {
            const float zj = sZ[lane];
            #pragma unroll
            for (int t = 0; t < 4; t++) {
                const int i = warp + 8 * t;
                if (i < NJ) {
                    const float S = lo2(accP[t]) + hi2(accP[t])
                                  + lo2(accQ[t]) + hi2(accQ[t]);
                    outB[i * NJ + lane] = c1 * (zj - sZ[i]) + c2 * S;
                }
            }
        }
    }
}

extern "C" void kernel_launch(void* const* d_in, const int* in_sizes, int n_in,
                              void* d_out, int out_size)
{
    // metadata order: src, heads, ends, pair_ids, W1, alpha, W2
    const float* src   = (const float*)d_in[0];
    const float* W1    = (const float*)d_in[4];
    const float* alpha = (const float*)d_in[5];
    const float* W2    = (const float*)d_in[6];
    float* out = (float*)d_out;

    cudaFuncSetAttribute(fused_edge_kernel,
                         cudaFuncAttributeMaxDynamicSharedMemorySize, SMEM_BYTES);

    const int batch = in_sizes[0] / (NJ * CIN);          // 256
    convert_w_kernel<<<(NW4 + 255) / 256, 256>>>(W1);
    fused_edge_kernel<<<batch, 256, SMEM_BYTES>>>(src, alpha, W2, out);
}